// round 12
// baseline (speedup 1.0000x reference)
#include <cuda_runtime.h>
#include <cuda_fp16.h>

#define HH 128
#define WW 128
#define CC 64
#define HD 8
#define NTOK 256

__device__ __forceinline__ unsigned tf32c(float f) {
    unsigned r; asm("cvt.rna.tf32.f32 %0, %1;" : "=r"(r) : "f"(f)); return r;
}
__device__ __forceinline__ float ex2f(float x) {
    float y; asm("ex2.approx.f32 %0, %1;" : "=f"(y) : "f"(x)); return y;
}
__device__ __forceinline__ void mma_tf32(float d[4], const unsigned a[4], uint2 b) {
    asm("mma.sync.aligned.m16n8k8.row.col.f32.tf32.tf32.f32 "
        "{%0,%1,%2,%3}, {%4,%5,%6,%7}, {%8,%9}, {%0,%1,%2,%3};"
        : "+f"(d[0]), "+f"(d[1]), "+f"(d[2]), "+f"(d[3])
        : "r"(a[0]), "r"(a[1]), "r"(a[2]), "r"(a[3]), "r"(b.x), "r"(b.y));
}
__device__ __forceinline__ void mma_f16(float d[4], const unsigned a[4],
                                        unsigned b0, unsigned b1) {
    asm("mma.sync.aligned.m16n8k16.row.col.f32.f16.f16.f32 "
        "{%0,%1,%2,%3}, {%4,%5,%6,%7}, {%8,%9}, {%0,%1,%2,%3};"
        : "+f"(d[0]), "+f"(d[1]), "+f"(d[2]), "+f"(d[3])
        : "r"(a[0]), "r"(a[1]), "r"(a[2]), "r"(a[3]), "r"(b0), "r"(b1));
}
__device__ __forceinline__ unsigned packh2(float lo, float hi) {
    __half2 h = __floats2half2_rn(lo, hi);
    return *(unsigned*)&h;
}

// One CTA = one (batch, window, head). 512 threads = 16 warps.
// Warp w owns S/O rows 16w..16w+15 (one m16 tile).
__global__ __launch_bounds__(512, 2) void lepe_kernel(
    const float* __restrict__ temp,   // (B,3,C,H,W) fp32
    const float* __restrict__ convw,  // (C,1,3,3)
    const float* __restrict__ convb,  // (C,)
    float* __restrict__ out)          // (B,H*W,C)
{
    __shared__ __align__(16) float2 Qpair[NTOK][4];   // (q[c], q[c+4]), scaled by C1
    __shared__ __align__(16) uint2  KpairH[NTOK][4];  // tf32(K), (c, c+4)
    __shared__ unsigned Vh2u[HD][132];                // half2 over token pairs (padded)
    __shared__ float Vrow[NTOK][HD];                  // fp32 V for LePE conv
    __shared__ float Wc[HD][9];
    __shared__ float Bc[HD];

    const int wi   = blockIdx.x & 63;
    const int head = (blockIdx.x >> 6) & 7;
    const int b    = blockIdx.x >> 9;
    const int t    = threadIdx.x;
    const int lane = t & 31;
    const int w    = t >> 5;
    const int q4   = lane & 3;
    const int r4   = lane >> 2;

    const size_t plane = (size_t)HH * WW;
    const float* qb = temp + ((size_t)b * 3 + 0) * CC * plane;
    const float* kb = temp + ((size_t)b * 3 + 1) * CC * plane;
    const float* vb = temp + ((size_t)b * 3 + 2) * CC * plane;
    const int colw = 2 * wi;
    const float C1 = 0.35355339059327373f * 1.4426950408889634f; // hd^-0.5 * log2(e)
    const unsigned ONESH2 = 0x3C003C00u;   // half2(1.0, 1.0)

    // ---- prologue: thread (t0, g) loads tokens 2t0, 2t0+1, pair-slot c=g ----
    {
        const int t0 = t & 127;
        const int g  = t >> 7;              // 0..3
        const int c  = g;
        const int dlo = g, dhi = g + 4;
        const size_t sp = (size_t)t0 * WW + colw;
        const float2 qlo = *(const float2*)(qb + (head*8 + dlo) * plane + sp);
        const float2 qhi = *(const float2*)(qb + (head*8 + dhi) * plane + sp);
        Qpair[2*t0  ][c] = make_float2(qlo.x * C1, qhi.x * C1);
        Qpair[2*t0+1][c] = make_float2(qlo.y * C1, qhi.y * C1);
        const float2 klo = *(const float2*)(kb + (head*8 + dlo) * plane + sp);
        const float2 khi = *(const float2*)(kb + (head*8 + dhi) * plane + sp);
        KpairH[2*t0  ][c] = make_uint2(tf32c(klo.x), tf32c(khi.x));
        KpairH[2*t0+1][c] = make_uint2(tf32c(klo.y), tf32c(khi.y));
        const float2 vlo = *(const float2*)(vb + (head*8 + dlo) * plane + sp);
        const float2 vhi = *(const float2*)(vb + (head*8 + dhi) * plane + sp);
        Vh2u[dlo][t0] = packh2(vlo.x, vlo.y);
        Vh2u[dhi][t0] = packh2(vhi.x, vhi.y);
        Vrow[2*t0  ][dlo] = vlo.x;  Vrow[2*t0+1][dlo] = vlo.y;
        Vrow[2*t0  ][dhi] = vhi.x;  Vrow[2*t0+1][dhi] = vhi.y;
    }
    if (t < 72) Wc[t/9][t%9] = convw[(head*8 + t/9)*9 + (t%9)];
    if (t < 8)  Bc[t] = convb[head*8 + t];
    __syncthreads();

    // ---- Q fragment (A of m16n8k8 tf32), split hi/lo (rows 16w..16w+15) ----
    unsigned QH[4], QL[4];
    {
        const int row0 = w*16 + r4;
        const float2 p0 = Qpair[row0    ][q4];   // (r, c), (r, c+4)
        const float2 p1 = Qpair[row0 + 8][q4];   // (r+8, c), (r+8, c+4)
        unsigned uh;
        uh = tf32c(p0.x); QH[0] = uh; QL[0] = tf32c(p0.x - __uint_as_float(uh));
        uh = tf32c(p1.x); QH[1] = uh; QL[1] = tf32c(p1.x - __uint_as_float(uh));
        uh = tf32c(p0.y); QH[2] = uh; QL[2] = tf32c(p0.y - __uint_as_float(uh));
        uh = tf32c(p1.y); QH[3] = uh; QL[3] = tf32c(p1.y - __uint_as_float(uh));
    }

    float O[4]    = {0.f, 0.f, 0.f, 0.f};
    float Dsum[4] = {0.f, 0.f, 0.f, 0.f};

    // ---- main loop: 16 tokens per step (two n8 S-tiles -> k16 PV + k16 sum mma) ----
    #pragma unroll
    for (int kt = 0; kt < 16; kt++) {
        const int tok0 = kt*16 + r4, tok1 = tok0 + 8;
        const uint2 bh0 = KpairH[tok0][q4], bh1 = KpairH[tok1][q4];
        const unsigned bv0 = Vh2u[r4][kt*8 + q4];
        const unsigned bv1 = Vh2u[r4][kt*8 + 4 + q4];

        float s0[4] = {0.f,0.f,0.f,0.f}, s1[4] = {0.f,0.f,0.f,0.f};
        mma_tf32(s0, QH, bh0);
        mma_tf32(s0, QL, bh0);
        mma_tf32(s1, QH, bh1);
        mma_tf32(s1, QL, bh1);

        unsigned a[4];
        a[0] = packh2(ex2f(s0[0]), ex2f(s0[1]));   // (r,   k 2q,2q+1)
        a[1] = packh2(ex2f(s0[2]), ex2f(s0[3]));   // (r+8, k 2q,2q+1)
        a[2] = packh2(ex2f(s1[0]), ex2f(s1[1]));   // (r,   k 8+2q,..)
        a[3] = packh2(ex2f(s1[2]), ex2f(s1[3]));   // (r+8, k 8+2q,..)
        mma_f16(O, a, bv0, bv1);
        mma_f16(Dsum, a, ONESH2, ONESH2);          // row sums via ones-column
    }

    // ---- epilogue: normalize, LePE conv, store ----
    #pragma unroll
    for (int rh = 0; rh < 2; rh++) {
        const float inv = 1.0f / Dsum[rh*2];       // all Dsum cols equal = row sum
        const int n  = w*16 + rh*8 + r4;
        const int h  = n >> 1, ws = n & 1;
        const int d0 = 2*q4, d1 = d0 + 1;
        float o0 = O[rh*2+0] * inv;
        float o1 = O[rh*2+1] * inv;

        float acc0 = Bc[d0], acc1 = Bc[d1];
        #pragma unroll
        for (int dh = -1; dh <= 1; dh++) {
            const int hh2 = h + dh;
            if (hh2 >= 0 && hh2 < HH) {
                const float va0 = Vrow[2*hh2][d0], vb0 = Vrow[2*hh2+1][d0];
                const float va1 = Vrow[2*hh2][d1], vb1 = Vrow[2*hh2+1][d1];
                const int bs = (dh+1)*3;
                if (ws == 0) {
                    acc0 += Wc[d0][bs+1]*va0 + Wc[d0][bs+2]*vb0;
                    acc1 += Wc[d1][bs+1]*va1 + Wc[d1][bs+2]*vb1;
                } else {
                    acc0 += Wc[d0][bs+0]*va0 + Wc[d0][bs+1]*vb0;
                    acc1 += Wc[d1][bs+0]*va1 + Wc[d1][bs+1]*vb1;
                }
            }
        }
        o0 += acc0; o1 += acc1;

        const size_t ob = (((size_t)b * plane) + (size_t)h * WW + (colw + ws)) * CC
                          + (size_t)head * 8 + d0;
        *(float2*)(out + ob) = make_float2(o0, o1);
    }
}

extern "C" void kernel_launch(void* const* d_in, const int* in_sizes, int n_in,
                              void* d_out, int out_size) {
    const float* temp = (const float*)d_in[0];
    const float* cw   = (const float*)d_in[1];
    const float* cb   = (const float*)d_in[2];
    float* out        = (float*)d_out;
    (void)in_sizes; (void)n_in; (void)out_size;
    lepe_kernel<<<4 * 64 * 8, 512>>>(temp, cw, cb, out);
}

// round 13
// speedup vs baseline: 1.0738x; 1.0738x over previous
#include <cuda_runtime.h>
#include <cuda_fp16.h>

#define HH 128
#define WW 128
#define CC 64
#define HD 8
#define NTOK 256

__device__ __forceinline__ unsigned tf32c(float f) {
    unsigned r; asm("cvt.rna.tf32.f32 %0, %1;" : "=r"(r) : "f"(f)); return r;
}
__device__ __forceinline__ float ex2f(float x) {
    float y; asm("ex2.approx.f32 %0, %1;" : "=f"(y) : "f"(x)); return y;
}
__device__ __forceinline__ void mma_tf32(float d[4], const unsigned a[4], uint2 b) {
    asm("mma.sync.aligned.m16n8k8.row.col.f32.tf32.tf32.f32 "
        "{%0,%1,%2,%3}, {%4,%5,%6,%7}, {%8,%9}, {%0,%1,%2,%3};"
        : "+f"(d[0]), "+f"(d[1]), "+f"(d[2]), "+f"(d[3])
        : "r"(a[0]), "r"(a[1]), "r"(a[2]), "r"(a[3]), "r"(b.x), "r"(b.y));
}
__device__ __forceinline__ void mma_f16(float d[4], const unsigned a[4],
                                        unsigned b0, unsigned b1) {
    asm("mma.sync.aligned.m16n8k16.row.col.f32.f16.f16.f32 "
        "{%0,%1,%2,%3}, {%4,%5,%6,%7}, {%8,%9}, {%0,%1,%2,%3};"
        : "+f"(d[0]), "+f"(d[1]), "+f"(d[2]), "+f"(d[3])
        : "r"(a[0]), "r"(a[1]), "r"(a[2]), "r"(a[3]), "r"(b0), "r"(b1));
}
__device__ __forceinline__ unsigned packh2(float lo, float hi) {
    __half2 h = __floats2half2_rn(lo, hi);
    return *(unsigned*)&h;
}

// One CTA = one (batch, window, head). 256 threads = 8 warps.
// Warp w owns S/O rows 32w..32w+31 (2 m16 tiles).
__global__ __launch_bounds__(256, 3) void lepe_kernel(
    const float* __restrict__ temp,   // (B,3,C,H,W) fp32
    const float* __restrict__ convw,  // (C,1,3,3)
    const float* __restrict__ convb,  // (C,)
    float* __restrict__ out)          // (B,H*W,C)
{
    __shared__ __align__(16) float2 Qpair[NTOK][4];    // (q[c], q[c+4]), scaled by C1
    __shared__ __align__(16) uint2  KF[16][32][2];     // K fragments: [kt][lane][half]
    __shared__ __align__(8)  unsigned VF[16][32][2];   // V fragments: [kt][lane][slot]
    __shared__ float Vrow[NTOK][HD];                   // fp32 V for LePE conv
    __shared__ float Wc[HD][9];
    __shared__ float Bc[HD];

    const int wi   = blockIdx.x & 63;
    const int head = (blockIdx.x >> 6) & 7;
    const int b    = blockIdx.x >> 9;
    const int t    = threadIdx.x;
    const int lane = t & 31;
    const int w    = t >> 5;
    const int q4   = lane & 3;
    const int r4   = lane >> 2;

    const size_t plane = (size_t)HH * WW;
    const float* qb = temp + ((size_t)b * 3 + 0) * CC * plane;
    const float* kb = temp + ((size_t)b * 3 + 1) * CC * plane;
    const float* vb = temp + ((size_t)b * 3 + 2) * CC * plane;
    const int colw = 2 * wi;
    const float C1 = 0.35355339059327373f * 1.4426950408889634f; // hd^-0.5 * log2(e)
    const unsigned ONESH2 = 0x3C003C00u;   // half2(1.0, 1.0)

    // ---- prologue: thread (t0, h2) loads tokens 2t0, 2t0+1, pair slots 2h2..2h2+1 ----
    {
        const int t0 = t & 127;
        const int h2 = t >> 7;
        const size_t sp = (size_t)t0 * WW + colw;
        const int kt0  = t0 >> 3;        // fragment kt for tokens 2t0, 2t0+1
        const int rr   = t0 & 3;         // (t0&3): token-octet index
        const int half = (t0 >> 2) & 1;  // K half / V slot selector
        #pragma unroll
        for (int ci = 0; ci < 2; ci++) {
            const int c   = 2 * h2 + ci;       // pair slot 0..3
            const int dlo = c, dhi = c + 4;
            const float2 qlo = *(const float2*)(qb + (head*8 + dlo) * plane + sp);
            const float2 qhi = *(const float2*)(qb + (head*8 + dhi) * plane + sp);
            Qpair[2*t0  ][c] = make_float2(qlo.x * C1, qhi.x * C1);
            Qpair[2*t0+1][c] = make_float2(qlo.y * C1, qhi.y * C1);
            const float2 klo = *(const float2*)(kb + (head*8 + dlo) * plane + sp);
            const float2 khi = *(const float2*)(kb + (head*8 + dhi) * plane + sp);
            // K fragment scatter: token n -> KF[n>>4][(n&7)*4 + c][(n>>3)&1]
            KF[kt0][8*rr     + c][half] = make_uint2(tf32c(klo.x), tf32c(khi.x)); // n=2t0
            KF[kt0][8*rr + 4 + c][half] = make_uint2(tf32c(klo.y), tf32c(khi.y)); // n=2t0+1
            const float2 vlo = *(const float2*)(vb + (head*8 + dlo) * plane + sp);
            const float2 vhi = *(const float2*)(vb + (head*8 + dhi) * plane + sp);
            // V fragment scatter: token-pair t0, channel d -> VF[t0>>3][d*4 + (t0&3)][(t0>>2)&1]
            VF[kt0][dlo*4 + rr][half] = packh2(vlo.x, vlo.y);
            VF[kt0][dhi*4 + rr][half] = packh2(vhi.x, vhi.y);
            Vrow[2*t0  ][dlo] = vlo.x;  Vrow[2*t0+1][dlo] = vlo.y;
            Vrow[2*t0  ][dhi] = vhi.x;  Vrow[2*t0+1][dhi] = vhi.y;
        }
    }
    if (t < 72) Wc[t/9][t%9] = convw[(head*8 + t/9)*9 + (t%9)];
    if (t < 8)  Bc[t] = convb[head*8 + t];
    __syncthreads();

    // ---- Q fragments (A of m16n8k8 tf32), split hi/lo, 2 m-tiles ----
    unsigned QH[2][4], QL[2][4];
    #pragma unroll
    for (int mt = 0; mt < 2; mt++) {
        const int row0 = w*32 + mt*16 + r4;
        const float2 p0 = Qpair[row0    ][q4];   // (r, c), (r, c+4)
        const float2 p1 = Qpair[row0 + 8][q4];   // (r+8, c), (r+8, c+4)
        unsigned uh;
        uh = tf32c(p0.x); QH[mt][0] = uh; QL[mt][0] = tf32c(p0.x - __uint_as_float(uh));
        uh = tf32c(p1.x); QH[mt][1] = uh; QL[mt][1] = tf32c(p1.x - __uint_as_float(uh));
        uh = tf32c(p0.y); QH[mt][2] = uh; QL[mt][2] = tf32c(p0.y - __uint_as_float(uh));
        uh = tf32c(p1.y); QH[mt][3] = uh; QL[mt][3] = tf32c(p1.y - __uint_as_float(uh));
    }

    float O[2][4], Dsum[2][4];
    #pragma unroll
    for (int mt = 0; mt < 2; mt++) {
        O[mt][0]=O[mt][1]=O[mt][2]=O[mt][3]=0.f;
        Dsum[mt][0]=Dsum[mt][1]=Dsum[mt][2]=Dsum[mt][3]=0.f;
    }

    // ---- main loop: 16 tokens/step; 1 LDS.128 + 1 LDS.64 per step ----
    #pragma unroll 2
    for (int kt = 0; kt < 16; kt++) {
        const uint4 kf = *(const uint4*)&KF[kt][lane][0];
        const uint2 bh0 = make_uint2(kf.x, kf.y);
        const uint2 bh1 = make_uint2(kf.z, kf.w);
        const uint2 vf = *(const uint2*)&VF[kt][lane][0];

        #pragma unroll
        for (int mt = 0; mt < 2; mt++) {
            float s0[4] = {0.f,0.f,0.f,0.f}, s1[4] = {0.f,0.f,0.f,0.f};
            mma_tf32(s0, QH[mt], bh0);
            mma_tf32(s0, QL[mt], bh0);
            mma_tf32(s1, QH[mt], bh1);
            mma_tf32(s1, QL[mt], bh1);

            unsigned a[4];
            a[0] = packh2(ex2f(s0[0]), ex2f(s0[1]));   // (r,   k 2q,2q+1)
            a[1] = packh2(ex2f(s0[2]), ex2f(s0[3]));   // (r+8, k 2q,2q+1)
            a[2] = packh2(ex2f(s1[0]), ex2f(s1[1]));   // (r,   k 8+2q,..)
            a[3] = packh2(ex2f(s1[2]), ex2f(s1[3]));   // (r+8, k 8+2q,..)
            mma_f16(O[mt], a, vf.x, vf.y);
            mma_f16(Dsum[mt], a, ONESH2, ONESH2);      // row sums via ones-column
        }
    }

    // ---- epilogue: normalize, LePE conv, store ----
    #pragma unroll
    for (int mt = 0; mt < 2; mt++) {
        #pragma unroll
        for (int rh = 0; rh < 2; rh++) {
            const float inv = 1.0f / Dsum[mt][rh*2];   // all Dsum cols equal = row sum
            const int n  = w*32 + mt*16 + rh*8 + r4;
            const int h  = n >> 1, ws = n & 1;
            const int d0 = 2*q4, d1 = d0 + 1;
            float o0 = O[mt][rh*2+0] * inv;
            float o1 = O[mt][rh*2+1] * inv;

            float acc0 = Bc[d0], acc1 = Bc[d1];
            #pragma unroll
            for (int dh = -1; dh <= 1; dh++) {
                const int hh2 = h + dh;
                if (hh2 >= 0 && hh2 < HH) {
                    const float va0 = Vrow[2*hh2][d0], vb0 = Vrow[2*hh2+1][d0];
                    const float va1 = Vrow[2*hh2][d1], vb1 = Vrow[2*hh2+1][d1];
                    const int bs = (dh+1)*3;
                    if (ws == 0) {
                        acc0 += Wc[d0][bs+1]*va0 + Wc[d0][bs+2]*vb0;
                        acc1 += Wc[d1][bs+1]*va1 + Wc[d1][bs+2]*vb1;
                    } else {
                        acc0 += Wc[d0][bs+0]*va0 + Wc[d0][bs+1]*vb0;
                        acc1 += Wc[d1][bs+0]*va1 + Wc[d1][bs+1]*vb1;
                    }
                }
            }
            o0 += acc0; o1 += acc1;

            const size_t ob = (((size_t)b * plane) + (size_t)h * WW + (colw + ws)) * CC
                              + (size_t)head * 8 + d0;
            *(float2*)(out + ob) = make_float2(o0, o1);
        }
    }
}

extern "C" void kernel_launch(void* const* d_in, const int* in_sizes, int n_in,
                              void* d_out, int out_size) {
    const float* temp = (const float*)d_in[0];
    const float* cw   = (const float*)d_in[1];
    const float* cb   = (const float*)d_in[2];
    float* out        = (float*)d_out;
    (void)in_sizes; (void)n_in; (void)out_size;
    lepe_kernel<<<4 * 64 * 8, 256>>>(temp, cw, cb, out);
}

// round 14
// speedup vs baseline: 1.1276x; 1.0500x over previous
#include <cuda_runtime.h>
#include <cuda_fp16.h>

#define HH 128
#define WW 128
#define CC 64
#define HD 8
#define NTOK 256

__device__ __forceinline__ unsigned tf32c(float f) {
    unsigned r; asm("cvt.rna.tf32.f32 %0, %1;" : "=r"(r) : "f"(f)); return r;
}
// pack two f32 -> half2 (lo, hi)
__device__ __forceinline__ unsigned cvth2(float hi, float lo) {
    unsigned r; asm("cvt.rn.f16x2.f32 %0, %1, %2;" : "=r"(r) : "f"(hi), "f"(lo)); return r;
}
// 2^x on both halves, one MUFU op
__device__ __forceinline__ unsigned h2ex2(unsigned x) {
    unsigned y; asm("ex2.approx.f16x2 %0, %1;" : "=r"(y) : "r"(x)); return y;
}
__device__ __forceinline__ void mma_tf32(float d[4], const unsigned a[4], uint2 b) {
    asm("mma.sync.aligned.m16n8k8.row.col.f32.tf32.tf32.f32 "
        "{%0,%1,%2,%3}, {%4,%5,%6,%7}, {%8,%9}, {%0,%1,%2,%3};"
        : "+f"(d[0]), "+f"(d[1]), "+f"(d[2]), "+f"(d[3])
        : "r"(a[0]), "r"(a[1]), "r"(a[2]), "r"(a[3]), "r"(b.x), "r"(b.y));
}
__device__ __forceinline__ void mma_f16(float d[4], const unsigned a[4],
                                        unsigned b0, unsigned b1) {
    asm("mma.sync.aligned.m16n8k16.row.col.f32.f16.f16.f32 "
        "{%0,%1,%2,%3}, {%4,%5,%6,%7}, {%8,%9}, {%0,%1,%2,%3};"
        : "+f"(d[0]), "+f"(d[1]), "+f"(d[2]), "+f"(d[3])
        : "r"(a[0]), "r"(a[1]), "r"(a[2]), "r"(a[3]), "r"(b0), "r"(b1));
}
__device__ __forceinline__ unsigned packh2(float lo, float hi) {
    __half2 h = __floats2half2_rn(lo, hi);
    return *(unsigned*)&h;
}

// One CTA = one (batch, window, head). 256 threads = 8 warps.
// Warp w owns S/O rows 32w..32w+31 (2 m16 tiles).
__global__ __launch_bounds__(256, 3) void lepe_kernel(
    const float* __restrict__ temp,   // (B,3,C,H,W) fp32
    const float* __restrict__ convw,  // (C,1,3,3)
    const float* __restrict__ convb,  // (C,)
    float* __restrict__ out)          // (B,H*W,C)
{
    __shared__ __align__(16) float2 Qpair[NTOK][4];    // (q[c], q[c+4]), scaled by C1
    __shared__ __align__(16) uint2  KF[16][32][2];     // K fragments: [kt][lane][half]
    __shared__ __align__(8)  unsigned VF[16][32][2];   // V fragments: [kt][lane][slot]
    __shared__ float Vrow[NTOK][HD];                   // fp32 V for LePE conv
    __shared__ float Wc[HD][9];
    __shared__ float Bc[HD];

    const int wi   = blockIdx.x & 63;
    const int head = (blockIdx.x >> 6) & 7;
    const int b    = blockIdx.x >> 9;
    const int t    = threadIdx.x;
    const int lane = t & 31;
    const int w    = t >> 5;
    const int q4   = lane & 3;
    const int r4   = lane >> 2;

    const size_t plane = (size_t)HH * WW;
    const float* qb = temp + ((size_t)b * 3 + 0) * CC * plane;
    const float* kb = temp + ((size_t)b * 3 + 1) * CC * plane;
    const float* vb = temp + ((size_t)b * 3 + 2) * CC * plane;
    const int colw = 2 * wi;
    const float C1 = 0.35355339059327373f * 1.4426950408889634f; // hd^-0.5 * log2(e)
    const unsigned ONESH2 = 0x3C003C00u;   // half2(1.0, 1.0)

    // ---- prologue: thread (t0, h2) loads tokens 2t0, 2t0+1, pair slots 2h2..2h2+1 ----
    {
        const int t0 = t & 127;
        const int h2 = t >> 7;
        const size_t sp = (size_t)t0 * WW + colw;
        const int kt0  = t0 >> 3;        // fragment kt for tokens 2t0, 2t0+1
        const int rr   = t0 & 3;         // token-octet index
        const int half = (t0 >> 2) & 1;  // K half / V slot selector
        #pragma unroll
        for (int ci = 0; ci < 2; ci++) {
            const int c   = 2 * h2 + ci;       // pair slot 0..3
            const int dlo = c, dhi = c + 4;
            const float2 qlo = *(const float2*)(qb + (head*8 + dlo) * plane + sp);
            const float2 qhi = *(const float2*)(qb + (head*8 + dhi) * plane + sp);
            Qpair[2*t0  ][c] = make_float2(qlo.x * C1, qhi.x * C1);
            Qpair[2*t0+1][c] = make_float2(qlo.y * C1, qhi.y * C1);
            const float2 klo = *(const float2*)(kb + (head*8 + dlo) * plane + sp);
            const float2 khi = *(const float2*)(kb + (head*8 + dhi) * plane + sp);
            // K fragment scatter: token n -> KF[n>>4][(n&7)*4 + c][(n>>3)&1]
            KF[kt0][8*rr     + c][half] = make_uint2(tf32c(klo.x), tf32c(khi.x)); // n=2t0
            KF[kt0][8*rr + 4 + c][half] = make_uint2(tf32c(klo.y), tf32c(khi.y)); // n=2t0+1
            const float2 vlo = *(const float2*)(vb + (head*8 + dlo) * plane + sp);
            const float2 vhi = *(const float2*)(vb + (head*8 + dhi) * plane + sp);
            // V fragment scatter: token-pair t0, channel d -> VF[t0>>3][d*4 + (t0&3)][(t0>>2)&1]
            VF[kt0][dlo*4 + rr][half] = packh2(vlo.x, vlo.y);
            VF[kt0][dhi*4 + rr][half] = packh2(vhi.x, vhi.y);
            Vrow[2*t0  ][dlo] = vlo.x;  Vrow[2*t0+1][dlo] = vlo.y;
            Vrow[2*t0  ][dhi] = vhi.x;  Vrow[2*t0+1][dhi] = vhi.y;
        }
    }
    if (t < 72) Wc[t/9][t%9] = convw[(head*8 + t/9)*9 + (t%9)];
    if (t < 8)  Bc[t] = convb[head*8 + t];
    __syncthreads();

    // ---- Q fragments (A of m16n8k8 tf32), split hi/lo, 2 m-tiles ----
    unsigned QH[2][4], QL[2][4];
    #pragma unroll
    for (int mt = 0; mt < 2; mt++) {
        const int row0 = w*32 + mt*16 + r4;
        const float2 p0 = Qpair[row0    ][q4];   // (r, c), (r, c+4)
        const float2 p1 = Qpair[row0 + 8][q4];   // (r+8, c), (r+8, c+4)
        unsigned uh;
        uh = tf32c(p0.x); QH[mt][0] = uh; QL[mt][0] = tf32c(p0.x - __uint_as_float(uh));
        uh = tf32c(p1.x); QH[mt][1] = uh; QL[mt][1] = tf32c(p1.x - __uint_as_float(uh));
        uh = tf32c(p0.y); QH[mt][2] = uh; QL[mt][2] = tf32c(p0.y - __uint_as_float(uh));
        uh = tf32c(p1.y); QH[mt][3] = uh; QL[mt][3] = tf32c(p1.y - __uint_as_float(uh));
    }

    float O[2][4], Dsum[2][4];
    #pragma unroll
    for (int mt = 0; mt < 2; mt++) {
        O[mt][0]=O[mt][1]=O[mt][2]=O[mt][3]=0.f;
        Dsum[mt][0]=Dsum[mt][1]=Dsum[mt][2]=Dsum[mt][3]=0.f;
    }

    // ---- main loop: 16 tokens/step; 1 LDS.128 + 1 LDS.64 per step ----
    #pragma unroll 2
    for (int kt = 0; kt < 16; kt++) {
        const uint4 kf = *(const uint4*)&KF[kt][lane][0];
        const uint2 bh0 = make_uint2(kf.x, kf.y);
        const uint2 bh1 = make_uint2(kf.z, kf.w);
        const uint2 vf = *(const uint2*)&VF[kt][lane][0];

        #pragma unroll
        for (int mt = 0; mt < 2; mt++) {
            float s0[4] = {0.f,0.f,0.f,0.f}, s1[4] = {0.f,0.f,0.f,0.f};
            mma_tf32(s0, QH[mt], bh0);
            mma_tf32(s0, QL[mt], bh0);
            mma_tf32(s1, QH[mt], bh1);
            mma_tf32(s1, QL[mt], bh1);

            // exp2 in f16x2: cvt packs the pair, one MUFU op does two exps,
            // output IS the half2 A-fragment (no pack step).
            unsigned a[4];
            a[0] = h2ex2(cvth2(s0[1], s0[0]));   // (r,   k 2q,2q+1)
            a[1] = h2ex2(cvth2(s0[3], s0[2]));   // (r+8, k 2q,2q+1)
            a[2] = h2ex2(cvth2(s1[1], s1[0]));   // (r,   k 8+2q,..)
            a[3] = h2ex2(cvth2(s1[3], s1[2]));   // (r+8, k 8+2q,..)
            mma_f16(O[mt], a, vf.x, vf.y);
            mma_f16(Dsum[mt], a, ONESH2, ONESH2);   // row sums via ones-column
        }
    }

    // ---- epilogue: normalize, LePE conv, store ----
    #pragma unroll
    for (int mt = 0; mt < 2; mt++) {
        #pragma unroll
        for (int rh = 0; rh < 2; rh++) {
            const float inv = 1.0f / Dsum[mt][rh*2];   // all Dsum cols equal = row sum
            const int n  = w*32 + mt*16 + rh*8 + r4;
            const int h  = n >> 1, ws = n & 1;
            const int d0 = 2*q4, d1 = d0 + 1;
            float o0 = O[mt][rh*2+0] * inv;
            float o1 = O[mt][rh*2+1] * inv;

            float acc0 = Bc[d0], acc1 = Bc[d1];
            #pragma unroll
            for (int dh = -1; dh <= 1; dh++) {
                const int hh2 = h + dh;
                if (hh2 >= 0 && hh2 < HH) {
                    const float va0 = Vrow[2*hh2][d0], vb0 = Vrow[2*hh2+1][d0];
                    const float va1 = Vrow[2*hh2][d1], vb1 = Vrow[2*hh2+1][d1];
                    const int bs = (dh+1)*3;
                    if (ws == 0) {
                        acc0 += Wc[d0][bs+1]*va0 + Wc[d0][bs+2]*vb0;
                        acc1 += Wc[d1][bs+1]*va1 + Wc[d1][bs+2]*vb1;
                    } else {
                        acc0 += Wc[d0][bs+0]*va0 + Wc[d0][bs+1]*vb0;
                        acc1 += Wc[d1][bs+0]*va1 + Wc[d1][bs+1]*vb1;
                    }
                }
            }
            o0 += acc0; o1 += acc1;

            const size_t ob = (((size_t)b * plane) + (size_t)h * WW + (colw + ws)) * CC
                              + (size_t)head * 8 + d0;
            *(float2*)(out + ob) = make_float2(o0, o1);
        }
    }
}

extern "C" void kernel_launch(void* const* d_in, const int* in_sizes, int n_in,
                              void* d_out, int out_size) {
    const float* temp = (const float*)d_in[0];
    const float* cw   = (const float*)d_in[1];
    const float* cb   = (const float*)d_in[2];
    float* out        = (float*)d_out;
    (void)in_sizes; (void)n_in; (void)out_size;
    lepe_kernel<<<4 * 64 * 8, 256>>>(temp, cw, cb, out);
}

// round 15
// speedup vs baseline: 1.2412x; 1.1008x over previous
#include <cuda_runtime.h>
#include <cuda_fp16.h>

#define HH 128
#define WW 128
#define CC 64
#define HD 8
#define NTOK 256

// pack two f32 -> half2: low half = lo, high half = hi
__device__ __forceinline__ unsigned cvth2(float hi, float lo) {
    unsigned r; asm("cvt.rn.f16x2.f32 %0, %1, %2;" : "=r"(r) : "f"(hi), "f"(lo)); return r;
}
// 2^x on both halves, one MUFU op
__device__ __forceinline__ unsigned h2ex2(unsigned x) {
    unsigned y; asm("ex2.approx.f16x2 %0, %1;" : "=r"(y) : "r"(x)); return y;
}
__device__ __forceinline__ void mma_f16(float d[4], const unsigned a[4],
                                        unsigned b0, unsigned b1) {
    asm("mma.sync.aligned.m16n8k16.row.col.f32.f16.f16.f32 "
        "{%0,%1,%2,%3}, {%4,%5,%6,%7}, {%8,%9}, {%0,%1,%2,%3};"
        : "+f"(d[0]), "+f"(d[1]), "+f"(d[2]), "+f"(d[3])
        : "r"(a[0]), "r"(a[1]), "r"(a[2]), "r"(a[3]), "r"(b0), "r"(b1));
}
__device__ __forceinline__ unsigned packh2(float lo, float hi) {
    __half2 h = __floats2half2_rn(lo, hi);
    return *(unsigned*)&h;
}

// One CTA = one (batch, window, head). 256 threads = 8 warps.
// Warp w owns S/O rows 32w..32w+31 (2 m16 tiles).
// QK via f16 m16n8k16: A = [qh | ql] (double-f16 Q), B = [kf16 | kf16] (b1 = b0).
__global__ __launch_bounds__(256, 4) void lepe_kernel(
    const float* __restrict__ temp,   // (B,3,C,H,W) fp32
    const float* __restrict__ convw,  // (C,1,3,3)
    const float* __restrict__ convb,  // (C,)
    float* __restrict__ out)          // (B,H*W,C)
{
    __shared__ __align__(16) float2 QF[NTOK][4];      // (q[2pc], q[2pc+1]) scaled by C1
    __shared__ __align__(8)  unsigned KFu[16][32][2]; // K f16 fragments: [kt][lane][tile]
    __shared__ __align__(8)  unsigned VF[16][32][2];  // V f16 fragments: [kt][lane][slot]
    __shared__ float Vrow[NTOK][HD];                  // fp32 V for LePE conv
    __shared__ float Wc[HD][9];
    __shared__ float Bc[HD];

    const int wi   = blockIdx.x & 63;
    const int head = (blockIdx.x >> 6) & 7;
    const int b    = blockIdx.x >> 9;
    const int t    = threadIdx.x;
    const int lane = t & 31;
    const int w    = t >> 5;
    const int q4   = lane & 3;
    const int r4   = lane >> 2;

    const size_t plane = (size_t)HH * WW;
    const float* qb = temp + ((size_t)b * 3 + 0) * CC * plane;
    const float* kb = temp + ((size_t)b * 3 + 1) * CC * plane;
    const float* vb = temp + ((size_t)b * 3 + 2) * CC * plane;
    const int colw = 2 * wi;
    const float C1 = 0.35355339059327373f * 1.4426950408889634f; // hd^-0.5 * log2(e)
    const unsigned ONESH2 = 0x3C003C00u;   // half2(1.0, 1.0)

    // ---- prologue: thread (t0, h2) loads tokens 2t0, 2t0+1, ch-pairs {2h2, 2h2+1} ----
    {
        const int t0 = t & 127;
        const int h2 = t >> 7;
        const size_t sp = (size_t)t0 * WW + colw;
        const int kt0  = t0 >> 3;        // fragment kt for tokens 2t0, 2t0+1
        const int rr   = t0 & 3;         // token-octet index
        const int half = (t0 >> 2) & 1;  // n8-tile / V slot selector
        #pragma unroll
        for (int ci = 0; ci < 2; ci++) {
            const int pc = 2 * h2 + ci;        // channel-pair 0..3 (ADJACENT channels)
            const int d0 = 2 * pc, d1 = d0 + 1;
            const float2 q0 = *(const float2*)(qb + (head*8 + d0) * plane + sp);
            const float2 q1 = *(const float2*)(qb + (head*8 + d1) * plane + sp);
            QF[2*t0  ][pc] = make_float2(q0.x * C1, q1.x * C1);
            QF[2*t0+1][pc] = make_float2(q0.y * C1, q1.y * C1);
            const float2 k0 = *(const float2*)(kb + (head*8 + d0) * plane + sp);
            const float2 k1 = *(const float2*)(kb + (head*8 + d1) * plane + sp);
            // K fragment: token n -> KFu[n>>4][4*(n&7) + pc][(n>>3)&1] = half2(k[d0], k[d1])
            KFu[kt0][8*rr     + pc][half] = packh2(k0.x, k1.x);   // n = 2t0
            KFu[kt0][8*rr + 4 + pc][half] = packh2(k0.y, k1.y);   // n = 2t0+1
            const float2 v0 = *(const float2*)(vb + (head*8 + d0) * plane + sp);
            const float2 v1 = *(const float2*)(vb + (head*8 + d1) * plane + sp);
            // V fragment: channel d, token-pair -> VF[kt][d*4 + rr][half]
            VF[kt0][d0*4 + rr][half] = packh2(v0.x, v0.y);
            VF[kt0][d1*4 + rr][half] = packh2(v1.x, v1.y);
            Vrow[2*t0  ][d0] = v0.x;  Vrow[2*t0+1][d0] = v0.y;
            Vrow[2*t0  ][d1] = v1.x;  Vrow[2*t0+1][d1] = v1.y;
        }
    }
    if (t < 72) Wc[t/9][t%9] = convw[(head*8 + t/9)*9 + (t%9)];
    if (t < 8)  Bc[t] = convb[head*8 + t];
    __syncthreads();

    // ---- Q fragments: A = [qh | ql] double-f16, per m-tile ----
    unsigned QA[2][4];
    #pragma unroll
    for (int mt = 0; mt < 2; mt++) {
        const int row0 = w*32 + mt*16 + r4;
        const float2 p0 = QF[row0    ][q4];   // (q[2q4], q[2q4+1]) row r
        const float2 p1 = QF[row0 + 8][q4];   // row r+8
        const unsigned h0 = cvth2(p0.y, p0.x);
        const unsigned h1 = cvth2(p1.y, p1.x);
        const float2 f0 = __half22float2(*(const __half2*)&h0);
        const float2 f1 = __half22float2(*(const __half2*)&h1);
        QA[mt][0] = h0;                                     // qh, row r
        QA[mt][1] = h1;                                     // qh, row r+8
        QA[mt][2] = cvth2(p0.y - f0.y, p0.x - f0.x);        // ql, row r
        QA[mt][3] = cvth2(p1.y - f1.y, p1.x - f1.x);        // ql, row r+8
    }

    float O[2][4], Dsum[2][4];
    #pragma unroll
    for (int mt = 0; mt < 2; mt++) {
        O[mt][0]=O[mt][1]=O[mt][2]=O[mt][3]=0.f;
        Dsum[mt][0]=Dsum[mt][1]=Dsum[mt][2]=Dsum[mt][3]=0.f;
    }

    // ---- main loop: 16 tokens/step; 2x LDS.64 per step ----
    #pragma unroll 2
    for (int kt = 0; kt < 16; kt++) {
        const uint2 kf = *(const uint2*)&KFu[kt][lane][0];   // .x = tile0 B, .y = tile1 B
        const uint2 vf = *(const uint2*)&VF[kt][lane][0];

        #pragma unroll
        for (int mt = 0; mt < 2; mt++) {
            float s0[4] = {0.f,0.f,0.f,0.f}, s1[4] = {0.f,0.f,0.f,0.f};
            mma_f16(s0, QA[mt], kf.x, kf.x);   // S tile tok0..7  (b1 = b0, replicated K)
            mma_f16(s1, QA[mt], kf.y, kf.y);   // S tile tok8..15

            unsigned a[4];
            a[0] = h2ex2(cvth2(s0[1], s0[0]));   // (r,   k 2q,2q+1)
            a[1] = h2ex2(cvth2(s0[3], s0[2]));   // (r+8, k 2q,2q+1)
            a[2] = h2ex2(cvth2(s1[1], s1[0]));   // (r,   k 8+2q,..)
            a[3] = h2ex2(cvth2(s1[3], s1[2]));   // (r+8, k 8+2q,..)
            mma_f16(O[mt], a, vf.x, vf.y);
            mma_f16(Dsum[mt], a, ONESH2, ONESH2);   // row sums via ones-column
        }
    }

    // ---- epilogue: normalize, LePE conv, store ----
    #pragma unroll
    for (int mt = 0; mt < 2; mt++) {
        #pragma unroll
        for (int rh = 0; rh < 2; rh++) {
            const float inv = 1.0f / Dsum[mt][rh*2];   // all Dsum cols equal = row sum
            const int n  = w*32 + mt*16 + rh*8 + r4;
            const int h  = n >> 1, ws = n & 1;
            const int d0 = 2*q4, d1 = d0 + 1;
            float o0 = O[mt][rh*2+0] * inv;
            float o1 = O[mt][rh*2+1] * inv;

            float acc0 = Bc[d0], acc1 = Bc[d1];
            #pragma unroll
            for (int dh = -1; dh <= 1; dh++) {
                const int hh2 = h + dh;
                if (hh2 >= 0 && hh2 < HH) {
                    const float va0 = Vrow[2*hh2][d0], vb0 = Vrow[2*hh2+1][d0];
                    const float va1 = Vrow[2*hh2][d1], vb1 = Vrow[2*hh2+1][d1];
                    const int bs = (dh+1)*3;
                    if (ws == 0) {
                        acc0 += Wc[d0][bs+1]*va0 + Wc[d0][bs+2]*vb0;
                        acc1 += Wc[d1][bs+1]*va1 + Wc[d1][bs+2]*vb1;
                    } else {
                        acc0 += Wc[d0][bs+0]*va0 + Wc[d0][bs+1]*vb0;
                        acc1 += Wc[d1][bs+0]*va1 + Wc[d1][bs+1]*vb1;
                    }
                }
            }
            o0 += acc0; o1 += acc1;

            const size_t ob = (((size_t)b * plane) + (size_t)h * WW + (colw + ws)) * CC
                              + (size_t)head * 8 + d0;
            *(float2*)(out + ob) = make_float2(o0, o1);
        }
    }
}

extern "C" void kernel_launch(void* const* d_in, const int* in_sizes, int n_in,
                              void* d_out, int out_size) {
    const float* temp = (const float*)d_in[0];
    const float* cw   = (const float*)d_in[1];
    const float* cb   = (const float*)d_in[2];
    float* out        = (float*)d_out;
    (void)in_sizes; (void)n_in; (void)out_size;
    lepe_kernel<<<4 * 64 * 8, 256>>>(temp, cw, cb, out);
}

// round 16
// speedup vs baseline: 1.6586x; 1.3363x over previous
#include <cuda_runtime.h>
#include <cuda_fp16.h>

#define HH 128
#define WW 128
#define CC 64
#define HD 8
#define NTOK 256

__device__ __forceinline__ unsigned cvth2(float hi, float lo) {
    unsigned r; asm("cvt.rn.f16x2.f32 %0, %1, %2;" : "=r"(r) : "f"(hi), "f"(lo)); return r;
}
__device__ __forceinline__ unsigned h2ex2(unsigned x) {
    unsigned y; asm("ex2.approx.f16x2 %0, %1;" : "=r"(y) : "r"(x)); return y;
}
__device__ __forceinline__ void mma_f16(float d[4], const unsigned a[4],
                                        unsigned b0, unsigned b1) {
    asm("mma.sync.aligned.m16n8k16.row.col.f32.f16.f16.f32 "
        "{%0,%1,%2,%3}, {%4,%5,%6,%7}, {%8,%9}, {%0,%1,%2,%3};"
        : "+f"(d[0]), "+f"(d[1]), "+f"(d[2]), "+f"(d[3])
        : "r"(a[0]), "r"(a[1]), "r"(a[2]), "r"(a[3]), "r"(b0), "r"(b1));
}
__device__ __forceinline__ unsigned packh2(float lo, float hi) {
    __half2 h = __floats2half2_rn(lo, hi);
    return *(unsigned*)&h;
}

// One CTA = one (batch, head, window-PAIR). 512 threads = 16 warps.
// Warps 0-7 -> window A, warps 8-15 -> window B; within a window each warp
// owns rows 32*w2..32*w2+31 (2 m16 tiles). QK via f16 m16n8k16 double-f16 Q.
__global__ __launch_bounds__(512, 2) void lepe_kernel(
    const float* __restrict__ temp,   // (B,3,C,H,W) fp32
    const float* __restrict__ convw,  // (C,1,3,3)
    const float* __restrict__ convb,  // (C,)
    float* __restrict__ out)          // (B,H*W,C)
{
    __shared__ __align__(16) float2 QF[2][NTOK][4];      // staging: (q[2pc], q[2pc+1])*C1
    __shared__ __align__(8)  unsigned KFu[2][16][32][2]; // K f16 fragments [wnd][kt][lane][tile]
    __shared__ __align__(8)  unsigned VF[2][16][32][2];  // V f16 fragments [wnd][kt][lane][slot]
    __shared__ float Wc[HD][9];
    __shared__ float Bc[HD];

    const int wp   = blockIdx.x & 31;          // window pair: columns 4wp..4wp+3
    const int head = (blockIdx.x >> 5) & 7;
    const int b    = blockIdx.x >> 8;
    const int t    = threadIdx.x;
    const int lane = t & 31;
    const int w    = t >> 5;                   // 0..15
    const int wnd  = w >> 3;                   // window within pair
    const int w2   = w & 7;                    // warp within window
    const int q4   = lane & 3;
    const int r4   = lane >> 2;

    const size_t plane = (size_t)HH * WW;
    const float* qb = temp + ((size_t)b * 3 + 0) * CC * plane;
    const float* kb = temp + ((size_t)b * 3 + 1) * CC * plane;
    const float* vb = temp + ((size_t)b * 3 + 2) * CC * plane;
    const float C1 = 0.35355339059327373f * 1.4426950408889634f; // hd^-0.5 * log2(e)
    const unsigned ONESH2 = 0x3C003C00u;       // half2(1.0, 1.0)

    // ---- prologue: thread (t0, g) loads row h=t0, channels {2g, 2g+1}, 4 columns
    //      via LDG.128 -> (.x,.y) = window A tokens (2t0, 2t0+1); (.z,.w) = window B
    {
        const int t0 = t & 127;
        const int g  = t >> 7;                 // channel-pair 0..3
        const size_t sp = (size_t)t0 * WW + 4 * wp;
        const int kt0  = t0 >> 3;
        const int rr   = t0 & 3;
        const int half = (t0 >> 2) & 1;
        const int d0 = 2 * g, d1 = d0 + 1;

        const float4 q0 = *(const float4*)(qb + (head*8 + d0) * plane + sp);
        const float4 q1 = *(const float4*)(qb + (head*8 + d1) * plane + sp);
        QF[0][2*t0  ][g] = make_float2(q0.x * C1, q1.x * C1);
        QF[0][2*t0+1][g] = make_float2(q0.y * C1, q1.y * C1);
        QF[1][2*t0  ][g] = make_float2(q0.z * C1, q1.z * C1);
        QF[1][2*t0+1][g] = make_float2(q0.w * C1, q1.w * C1);

        const float4 k0 = *(const float4*)(kb + (head*8 + d0) * plane + sp);
        const float4 k1 = *(const float4*)(kb + (head*8 + d1) * plane + sp);
        KFu[0][kt0][8*rr     + g][half] = packh2(k0.x, k1.x);   // n = 2t0
        KFu[0][kt0][8*rr + 4 + g][half] = packh2(k0.y, k1.y);   // n = 2t0+1
        KFu[1][kt0][8*rr     + g][half] = packh2(k0.z, k1.z);
        KFu[1][kt0][8*rr + 4 + g][half] = packh2(k0.w, k1.w);

        const float4 v0 = *(const float4*)(vb + (head*8 + d0) * plane + sp);
        const float4 v1 = *(const float4*)(vb + (head*8 + d1) * plane + sp);
        VF[0][kt0][d0*4 + rr][half] = packh2(v0.x, v0.y);   // (V[2t0][d0], V[2t0+1][d0])
        VF[0][kt0][d1*4 + rr][half] = packh2(v1.x, v1.y);
        VF[1][kt0][d0*4 + rr][half] = packh2(v0.z, v0.w);
        VF[1][kt0][d1*4 + rr][half] = packh2(v1.z, v1.w);
    }
    if (t < 72) Wc[t/9][t%9] = convw[(head*8 + t/9)*9 + (t%9)];
    if (t < 8)  Bc[t] = convb[head*8 + t];
    __syncthreads();

    // ---- Q fragments: A = [qh | ql] double-f16, per m-tile ----
    unsigned QA[2][4];
    #pragma unroll
    for (int mt = 0; mt < 2; mt++) {
        const int row0 = w2*32 + mt*16 + r4;
        const float2 p0 = QF[wnd][row0    ][q4];   // (q[2q4], q[2q4+1]) row r
        const float2 p1 = QF[wnd][row0 + 8][q4];   // row r+8
        const unsigned h0 = cvth2(p0.y, p0.x);
        const unsigned h1 = cvth2(p1.y, p1.x);
        const float2 f0 = __half22float2(*(const __half2*)&h0);
        const float2 f1 = __half22float2(*(const __half2*)&h1);
        QA[mt][0] = h0;                                 // qh, row r
        QA[mt][1] = h1;                                 // qh, row r+8
        QA[mt][2] = cvth2(p0.y - f0.y, p0.x - f0.x);    // ql, row r
        QA[mt][3] = cvth2(p1.y - f1.y, p1.x - f1.x);    // ql, row r+8
    }

    float O[2][4], Dsum[2][4];
    #pragma unroll
    for (int mt = 0; mt < 2; mt++) {
        O[mt][0]=O[mt][1]=O[mt][2]=O[mt][3]=0.f;
        Dsum[mt][0]=Dsum[mt][1]=Dsum[mt][2]=Dsum[mt][3]=0.f;
    }

    // ---- main loop: 16 tokens/step; 2x LDS.64 per step ----
    #pragma unroll 2
    for (int kt = 0; kt < 16; kt++) {
        const uint2 kf = *(const uint2*)&KFu[wnd][kt][lane][0];  // two n8-tile B frags
        const uint2 vf = *(const uint2*)&VF[wnd][kt][lane][0];

        #pragma unroll
        for (int mt = 0; mt < 2; mt++) {
            float s0[4] = {0.f,0.f,0.f,0.f}, s1[4] = {0.f,0.f,0.f,0.f};
            mma_f16(s0, QA[mt], kf.x, kf.x);   // S tile tok 0..7  (b1 = b0, replicated K)
            mma_f16(s1, QA[mt], kf.y, kf.y);   // S tile tok 8..15

            unsigned a[4];
            a[0] = h2ex2(cvth2(s0[1], s0[0]));   // (r,   k 2q,2q+1)
            a[1] = h2ex2(cvth2(s0[3], s0[2]));   // (r+8, k 2q,2q+1)
            a[2] = h2ex2(cvth2(s1[1], s1[0]));   // (r,   k 8+2q,..)
            a[3] = h2ex2(cvth2(s1[3], s1[2]));   // (r+8, k 8+2q,..)
            mma_f16(O[mt], a, vf.x, vf.y);
            mma_f16(Dsum[mt], a, ONESH2, ONESH2);   // row sums via ones-column
        }
    }

    // ---- epilogue: normalize, LePE conv (V from f16 fragments), store ----
    const int colw = 4 * wp + 2 * wnd;
    #pragma unroll
    for (int mt = 0; mt < 2; mt++) {
        #pragma unroll
        for (int rh = 0; rh < 2; rh++) {
            const float inv = 1.0f / Dsum[mt][rh*2];
            const int n  = w2*32 + mt*16 + rh*8 + r4;
            const int h  = n >> 1, ws = n & 1;
            const int d0 = 2*q4, d1 = d0 + 1;
            float o0 = O[mt][rh*2+0] * inv;
            float o1 = O[mt][rh*2+1] * inv;

            float acc0 = Bc[d0], acc1 = Bc[d1];
            #pragma unroll
            for (int dh = -1; dh <= 1; dh++) {
                const int hh2 = h + dh;
                if (hh2 >= 0 && hh2 < HH) {
                    // VF[wnd][hh2>>3][d*4 + (hh2&3)][(hh2>>2)&1] = half2(V[2hh2][d], V[2hh2+1][d])
                    const unsigned u0 = VF[wnd][hh2>>3][d0*4 + (hh2&3)][(hh2>>2)&1];
                    const unsigned u1 = VF[wnd][hh2>>3][d1*4 + (hh2&3)][(hh2>>2)&1];
                    const float2 f0 = __half22float2(*(const __half2*)&u0);  // (va0, vb0)
                    const float2 f1 = __half22float2(*(const __half2*)&u1);  // (va1, vb1)
                    const int bs = (dh+1)*3;
                    if (ws == 0) {
                        acc0 += Wc[d0][bs+1]*f0.x + Wc[d0][bs+2]*f0.y;
                        acc1 += Wc[d1][bs+1]*f1.x + Wc[d1][bs+2]*f1.y;
                    } else {
                        acc0 += Wc[d0][bs+0]*f0.x + Wc[d0][bs+1]*f0.y;
                        acc1 += Wc[d1][bs+0]*f1.x + Wc[d1][bs+1]*f1.y;
                    }
                }
            }
            o0 += acc0; o1 += acc1;

            const size_t ob = (((size_t)b * plane) + (size_t)h * WW + (colw + ws)) * CC
                              + (size_t)head * 8 + d0;
            *(float2*)(out + ob) = make_float2(o0, o1);
        }
    }
}

extern "C" void kernel_launch(void* const* d_in, const int* in_sizes, int n_in,
                              void* d_out, int out_size) {
    const float* temp = (const float*)d_in[0];
    const float* cw   = (const float*)d_in[1];
    const float* cb   = (const float*)d_in[2];
    float* out        = (float*)d_out;
    (void)in_sizes; (void)n_in; (void)out_size;
    lepe_kernel<<<4 * 8 * 32, 512>>>(temp, cw, cb, out);
}